// round 17
// baseline (speedup 1.0000x reference)
#include <cuda_runtime.h>
#include <cuda_fp16.h>
#include <cstdint>

#define HID 128
#define NMAX 100000
#define CAP 32
#define WSH 144         // W smem stride in halves (288 B) -> conflict-free
#define NCTA 444        // 3 CTAs/SM x 148 SMs (EVEN: col-half fixed per CTA)

// scratch (no cudaMalloc allowed). g_cnt zero at module load; k_fused
// re-zeroes it every run so each execution starts from zeroed counters.
static __device__ __half g_hh[(size_t)2 * NMAX * HID];   // 51.2 MB (S,I fp16)
static __device__ int    g_cnt[NMAX];
static __device__ int    g_csr[(size_t)NMAX * CAP];      // 12.8 MB

__device__ __forceinline__ unsigned f2h2(float x, float y) {
    __half2 h = __floats2half2_rn(x, y);
    return *(unsigned*)&h;
}

// m16n8k16 fp16 MMA, f32 accum
__device__ __forceinline__ void mma_f16(float* acc, unsigned a0, unsigned a1,
                                        unsigned a2, unsigned a3,
                                        unsigned b0, unsigned b1) {
    asm volatile(
        "mma.sync.aligned.m16n8k16.row.col.f32.f16.f16.f32 "
        "{%0,%1,%2,%3}, {%4,%5,%6,%7}, {%8,%9}, {%0,%1,%2,%3};"
        : "+f"(acc[0]), "+f"(acc[1]), "+f"(acc[2]), "+f"(acc[3])
        : "r"(a0), "r"(a1), "r"(a2), "r"(a3), "r"(b0), "r"(b1));
}

// Persistent GEMM + edge fill (R15 structure; h now stored fp16).
__global__ __launch_bounds__(256, 3) void k_gemm_fill(
    const float* __restrict__ A, const float* __restrict__ W,
    const float* __restrict__ bias, int M,
    const int* __restrict__ er, const int* __restrict__ ec, int E, int n) {
    extern __shared__ __half Ws[];   // 64 x WSH halves = 18.4 KB
    int tid = threadIdx.x;
    int bid = blockIdx.x;
    int chh = bid & 1;               // this CTA's col half (fixed)

    // --- edge fill slice ---
    for (int e = bid * 256 + tid; e < E; e += NCTA * 256) {
        int r = er[e];
        int c = ec[e];
        if ((unsigned)r < (unsigned)n && (unsigned)c < (unsigned)n) {
            int pos = atomicAdd(&g_cnt[r], 1) & (CAP - 1);
            g_csr[(size_t)r * CAP + pos] = c;
        }
    }

    // --- stage this CTA's W half (64 rows) as fp16 ---
    for (int i = tid; i < 64 * 32; i += 256) {
        int r = i >> 5, s = i & 31;
        float4 v = *(const float4*)(W + (chh * 64 + r) * HID + s * 4);
        *(uint2*)(Ws + r * WSH + s * 4) = make_uint2(f2h2(v.x, v.y), f2h2(v.z, v.w));
    }
    __syncthreads();

    int w = tid >> 5, lane = tid & 31;
    int gid = lane >> 2, tig = lane & 3;
    int rw = w >> 1;            // row-warp 0..3 -> rows rw*32..+31
    int cw = w & 1;             // col warp 0..1 -> cols cw*32..+31 (in half)
    const __half* Wb = Ws + (cw * 32) * WSH;

    int ntiles = (M + 127) >> 7;
    for (int u = bid; u < 2 * ntiles; u += NCTA) {
        int t = u >> 1;                        // (u&1)==chh by construction
        int row = t * 128 + rw * 32 + gid;     // + {0,8,16,24}
        const float4* A0p = (const float4*)(A + (size_t)row * HID);
        const float4* A1p = (const float4*)(A + (size_t)(row + 8) * HID);
        const float4* A2p = (const float4*)(A + (size_t)(row + 16) * HID);
        const float4* A3p = (const float4*)(A + (size_t)(row + 24) * HID);

        float acc[4][2][4];
#pragma unroll
        for (int nt = 0; nt < 4; nt++)
#pragma unroll
            for (int p = 0; p < 2; p++)
                acc[nt][p][0] = acc[nt][p][1] = acc[nt][p][2] = acc[nt][p][3] = 0.f;

        // rows beyond M read into R region of x — finite garbage, never stored
#pragma unroll
        for (int c16 = 0; c16 < 8; c16++) {
            float4 v0 = A0p[c16 * 4 + tig];
            float4 v1 = A1p[c16 * 4 + tig];
            float4 v2 = A2p[c16 * 4 + tig];
            float4 v3 = A3p[c16 * 4 + tig];
            unsigned a00 = f2h2(v0.x, v0.y), a02 = f2h2(v0.z, v0.w);
            unsigned a01 = f2h2(v1.x, v1.y), a03 = f2h2(v1.z, v1.w);
            unsigned a10 = f2h2(v2.x, v2.y), a12 = f2h2(v2.z, v2.w);
            unsigned a11 = f2h2(v3.x, v3.y), a13 = f2h2(v3.z, v3.w);
#pragma unroll
            for (int nt = 0; nt < 4; nt++) {
                uint2 wv = *(const uint2*)(Wb + (nt * 8 + gid) * WSH + c16 * 16 + tig * 4);
                mma_f16(acc[nt][0], a00, a01, a02, a03, wv.x, wv.y);
                mma_f16(acc[nt][1], a10, a11, a12, a13, wv.x, wv.y);
            }
        }

#pragma unroll
        for (int nt = 0; nt < 4; nt++) {
            int col = chh * 64 + cw * 32 + nt * 8 + tig * 2;
            float bc0 = __ldg(bias + col), bc1 = __ldg(bias + col + 1);
#pragma unroll
            for (int p = 0; p < 2; p++) {
                int r0 = row + p * 16;
                if (r0 < M)
                    *(__half2*)(g_hh + (size_t)r0 * HID + col) =
                        __floats2half2_rn(fmaxf(acc[nt][p][0] + bc0, 0.f),
                                          fmaxf(acc[nt][p][1] + bc1, 0.f));
                if (r0 + 8 < M)
                    *(__half2*)(g_hh + (size_t)(r0 + 8) * HID + col) =
                        __floats2half2_rn(fmaxf(acc[nt][p][2] + bc0, 0.f),
                                          fmaxf(acc[nt][p][3] + bc1, 0.f));
            }
        }
    }
}

__device__ __forceinline__ void cvt8(float* f, uint4 u) {
    float2 p;
    p = __half22float2(*(__half2*)&u.x); f[0] = p.x; f[1] = p.y;
    p = __half22float2(*(__half2*)&u.y); f[2] = p.x; f[3] = p.y;
    p = __half22float2(*(__half2*)&u.z); f[4] = p.x; f[5] = p.y;
    p = __half22float2(*(__half2*)&u.w); f[6] = p.x; f[7] = p.y;
}

__device__ __forceinline__ void add8(float* a, uint4 u) {
    float2 p;
    p = __half22float2(*(__half2*)&u.x); a[0] += p.x; a[1] += p.y;
    p = __half22float2(*(__half2*)&u.y); a[2] += p.x; a[3] += p.y;
    p = __half22float2(*(__half2*)&u.z); a[4] += p.x; a[5] += p.y;
    p = __half22float2(*(__half2*)&u.w); a[6] += p.x; a[7] += p.y;
}

// One warp per node. fp16 rows are 256 B = 16 lanes x uint4, so the two
// half-warps (sel = lane>>4) cover TWO rows per load step: S+I together,
// and gathered neighbors in pairs. Every load stays 16 B (the R13 failure
// was load width, not data width). Lane owns 8 columns (hl*8..+7); values
// are duplicated across half-warps, so warp-wide moment sums use 1/256.
__global__ __launch_bounds__(256) void k_fused(
    const float* __restrict__ x, const float* __restrict__ lnw,
    const float* __restrict__ lnb, float* __restrict__ out, int n) {
    int warp = threadIdx.x >> 5, lane = threadIdx.x & 31;
    int i = blockIdx.x * 8 + warp;
    if (i >= n) return;
    int hl = lane & 15, sel = lane >> 4;

    const uint4*  hh4 = (const uint4*)g_hh;    // 16 uint4 per row
    const float4* x4 = (const float4*)x;
    float4* o4 = (float4*)out;

    // S (low half) + I (high half) in one load, then exchange
    uint4 usi = hh4[((size_t)i + (size_t)sel * n) * 16 + hl];
    float f[8]; cvt8(f, usi);
    float Sv[8], Iv[8];
#pragma unroll
    for (int k = 0; k < 8; k++) {
        float o = __shfl_xor_sync(0xffffffffu, f[k], 16);
        Sv[k] = sel ? o : f[k];
        Iv[k] = sel ? f[k] : o;
    }

    float4 X = __ldcs(&x4[((size_t)3 * n + i) * 32 + lane]);
    float beta = __shfl_sync(0xffffffffu, X.x, 0);
    float gam  = __shfl_sync(0xffffffffu, X.y, 0);

    int deg = min(g_cnt[i], CAP);
    if (lane == 0) g_cnt[i] = 0;                 // restore invariant for next run
    int c = (lane < deg) ? g_csr[(size_t)i * CAP + lane] : 0;

    // gather: 2 neighbors per load step (one per half-warp), 2 steps in flight
    float Aa[8] = {0, 0, 0, 0, 0, 0, 0, 0};
    float Ab[8] = {0, 0, 0, 0, 0, 0, 0, 0};
    int j = 0;
    for (; j + 4 <= deg; j += 4) {
        int ca = __shfl_sync(0xffffffffu, c, j + sel);
        int cb = __shfl_sync(0xffffffffu, c, j + 2 + sel);
        uint4 ua = hh4[((size_t)n + ca) * 16 + hl];
        uint4 ub = hh4[((size_t)n + cb) * 16 + hl];
        add8(Aa, ua);
        add8(Ab, ub);
    }
    if (j + 2 <= deg) {
        int ca = __shfl_sync(0xffffffffu, c, j + sel);
        uint4 ua = hh4[((size_t)n + ca) * 16 + hl];
        add8(Aa, ua);
        j += 2;
    }
    if (j < deg) {                      // odd tail: low half only
        int ca = __shfl_sync(0xffffffffu, c, j);
        if (sel == 0) {
            uint4 ua = hh4[((size_t)n + ca) * 16 + hl];
            add8(Ab, ua);
        }
    }
    float AI[8];
#pragma unroll
    for (int k = 0; k < 8; k++) {
        float s = Aa[k] + Ab[k];
        AI[k] = s + __shfl_xor_sync(0xffffffffu, s, 16);
    }

    float dS[8], dI[8], dR[8];
#pragma unroll
    for (int k = 0; k < 8; k++) {
        dS[k] = -beta * AI[k] * Sv[k];
        dI[k] = -dS[k] - gam * Iv[k];
        dR[k] = gam * Iv[k];
    }

    // six moment sums (values duplicated across half-warps -> 1/256 scale)
    float sa1 = 0.f, sa2 = 0.f, sb1 = 0.f, sb2 = 0.f, sc1 = 0.f, sc2 = 0.f;
#pragma unroll
    for (int k = 0; k < 8; k++) {
        sa1 += dS[k]; sa2 += dS[k] * dS[k];
        sb1 += dI[k]; sb2 += dI[k] * dI[k];
        sc1 += dR[k]; sc2 += dR[k] * dR[k];
    }
#pragma unroll
    for (int o = 16; o; o >>= 1) {
        sa1 += __shfl_xor_sync(0xffffffffu, sa1, o);
        sa2 += __shfl_xor_sync(0xffffffffu, sa2, o);
        sb1 += __shfl_xor_sync(0xffffffffu, sb1, o);
        sb2 += __shfl_xor_sync(0xffffffffu, sb2, o);
        sc1 += __shfl_xor_sync(0xffffffffu, sc1, o);
        sc2 += __shfl_xor_sync(0xffffffffu, sc2, o);
    }
    float ma = sa1 * (1.f / 256.f), mb = sb1 * (1.f / 256.f), mc = sc1 * (1.f / 256.f);
    float ra = rsqrtf(fmaxf(sa2 * (1.f / 256.f) - ma * ma, 0.f) + 1e-5f);
    float rb = rsqrtf(fmaxf(sb2 * (1.f / 256.f) - mb * mb, 0.f) + 1e-5f);
    float rc = rsqrtf(fmaxf(sc2 * (1.f / 256.f) - mc * mc, 0.f) + 1e-5f);

    // lane stores float4 #(2*hl + sel) of each output row (cols 8hl+4sel..+3)
    int fi = 2 * hl + sel;
    int kb = 4 * sel;
    float4 lwv = __ldg((const float4*)lnw + fi);
    float4 lbv = __ldg((const float4*)lnb + fi);

    __stcs(&o4[(size_t)i * 32 + fi],
           make_float4((dS[kb] - ma) * ra * lwv.x + lbv.x,
                       (dS[kb + 1] - ma) * ra * lwv.y + lbv.y,
                       (dS[kb + 2] - ma) * ra * lwv.z + lbv.z,
                       (dS[kb + 3] - ma) * ra * lwv.w + lbv.w));
    __stcs(&o4[((size_t)n + i) * 32 + fi],
           make_float4((dI[kb] - mb) * rb * lwv.x + lbv.x,
                       (dI[kb + 1] - mb) * rb * lwv.y + lbv.y,
                       (dI[kb + 2] - mb) * rb * lwv.z + lbv.z,
                       (dI[kb + 3] - mb) * rb * lwv.w + lbv.w));
    __stcs(&o4[((size_t)2 * n + i) * 32 + fi],
           make_float4((dR[kb] - mc) * rc * lwv.x + lbv.x,
                       (dR[kb + 1] - mc) * rc * lwv.y + lbv.y,
                       (dR[kb + 2] - mc) * rc * lwv.z + lbv.z,
                       (dR[kb + 3] - mc) * rc * lwv.w + lbv.w));
    __stcs(&o4[((size_t)3 * n + i) * 32 + lane], X);
}

extern "C" void kernel_launch(void* const* d_in, const int* in_sizes, int n_in,
                              void* d_out, int out_size) {
    // inputs: t, x, edge_row, edge_col, W, b, ln_w, ln_b (t unused)
    const float* x   = (const float*)d_in[1];
    const int*   er  = (const int*)d_in[2];
    const int*   ec  = (const int*)d_in[3];
    const float* W   = (const float*)d_in[4];
    const float* b   = (const float*)d_in[5];
    const float* lnw = (const float*)d_in[6];
    const float* lnb = (const float*)d_in[7];
    float* out = (float*)d_out;

    int n = (in_sizes[1] / HID) / 4;
    int E = in_sizes[2];
    int M = 2 * n;  // only S and I rows of h are ever used

    const int SMEM = 64 * WSH * 2;   // 18.4 KB fp16 W half
    cudaFuncSetAttribute(k_gemm_fill, cudaFuncAttributeMaxDynamicSharedMemorySize, SMEM);
    k_gemm_fill<<<NCTA, 256, SMEM>>>(x, W, b, M, er, ec, E, n);

    k_fused<<<(n + 7) / 8, 256>>>(x, lnw, lnb, out, n);
}